// round 14
// baseline (speedup 1.0000x reference)
#include <cuda_runtime.h>
#include <cuda_fp16.h>
#include <cstdint>

#define EMB 64
#define IN_DIM 32
#define NKV 2112              // (IN_DIM+1)*EMB : V col c = d*64+e, d=32 -> bias
#define MAX_NODES 50000
#define MAX_EDGES 150000
#define NBINS MAX_NODES
#define SCAN_NB ((NBINS + 255) / 256)

// Scratch (__device__ globals; allocation-free rule)
__device__ __half g_hp[MAX_NODES * EMB];           // fp16 h
__device__ __half g_wp[NKV * EMB];                 // fp16 W3T, [c][f]
__device__ __half g_V[(size_t)MAX_NODES * NKV];    // fp16 V (~211 MB)
__device__ float g_aggr[MAX_NODES * EMB];
__device__ int   g_src[MAX_EDGES];
__device__ int   g_tgt[MAX_EDGES];
__device__ int   g_eord[MAX_EDGES];
__device__ int   g_cnt[NBINS];
__device__ int   g_off[NBINS];
__device__ int   g_bsum[SCAN_NB];
__device__ int   g_boff[SCAN_NB];
__device__ int   g_idx_is64;

__device__ __forceinline__ uint32_t smem_u32(const void* p) {
    uint32_t a;
    asm("{ .reg .u64 t; cvta.to.shared.u64 t, %1; cvt.u32.u64 %0, t; }" : "=r"(a) : "l"(p));
    return a;
}

// ---------------------------------------------------------------------------
__global__ void probe_idx_kernel(const int* __restrict__ ei32, int M) {
    int n = 2 * M;
    int is64 = 1;
    for (int i = 1; i < 256 && i < n; i += 2)
        if (ei32[i] != 0) { is64 = 0; break; }
    g_idx_is64 = is64;
}

// Convert indices AND build the tgt histogram in the same pass.
__global__ void convert_hist_kernel(const void* __restrict__ eidx, int M) {
    int i = blockIdx.x * blockDim.x + threadIdx.x;
    if (i >= M) return;
    int s, t;
    if (g_idx_is64) {
        const long long* p = (const long long*)eidx;
        s = (int)p[i];
        t = (int)p[M + i];
    } else {
        const int* p = (const int*)eidx;
        s = p[i];
        t = p[M + i];
    }
    g_src[i] = s;
    g_tgt[i] = t;
    atomicAdd(&g_cnt[t], 1);
}

// Fused: fp16 h AND residual init of aggr (h read once).
__global__ void pack_h_init_kernel(const float* __restrict__ h, int n) {
    int i = blockIdx.x * blockDim.x + threadIdx.x;
    if (i >= n) return;
    float v = h[i];
    g_hp[i] = __float2half(v);
    g_aggr[i] = v;
}

// col c=(d,e): d<32 -> W[(e*64+f)*32+d] ; d==32 -> b[e*64+f]
// Also zeroes the sort histograms (saves a launch).
__global__ void pack_w_zero_kernel(const float* __restrict__ W, const float* __restrict__ b) {
    int idx = blockIdx.x * blockDim.x + threadIdx.x;
    if (idx < NBINS) g_cnt[idx] = 0;
    if (idx < SCAN_NB) g_bsum[idx] = 0;
    if (idx >= NKV * EMB) return;
    int c = idx >> 6, f = idx & 63;
    int d = c >> 6, e = c & 63;
    float w = (d < 32) ? W[(e * 64 + f) * 32 + d] : b[e * 64 + f];
    g_wp[idx] = __float2half(w);
}

// ---------------------------------------------------------------------------
// Stage 1: V = h @ W3T via single-pass mma.sync m16n8k16 fp16 (fp32 accum).
// Block 128 nodes x 128 cols, 8 warps (4m x 2n), warp tile 32 x 64.
__device__ __forceinline__ void mma_f16(float* d, const uint32_t* a, const uint32_t* b) {
    asm volatile(
        "mma.sync.aligned.m16n8k16.row.col.f32.f16.f16.f32 "
        "{%0,%1,%2,%3}, {%4,%5,%6,%7}, {%8,%9}, {%0,%1,%2,%3};"
        : "+f"(d[0]), "+f"(d[1]), "+f"(d[2]), "+f"(d[3])
        : "r"(a[0]), "r"(a[1]), "r"(a[2]), "r"(a[3]), "r"(b[0]), "r"(b[1]));
}
#define LDSM_X4(r0,r1,r2,r3,addr) \
    asm volatile("ldmatrix.sync.aligned.m8n8.x4.shared.b16 {%0,%1,%2,%3}, [%4];" \
        : "=r"(r0), "=r"(r1), "=r"(r2), "=r"(r3) : "r"(addr))

#define SPITCH 72             // fp16 per smem row (144 bytes)

__global__ __launch_bounds__(256) void node_v_mma_kernel(int N)
{
    __shared__ __align__(16) __half sA[128 * SPITCH];
    __shared__ __align__(16) __half sB[128 * SPITCH];

    const int tid  = threadIdx.x;
    const int w    = tid >> 5;
    const int lane = tid & 31;
    const int tq   = lane >> 2;
    const int tr   = lane & 3;
    const int m0   = blockIdx.x * 128;
    const int n0   = blockIdx.y * 128;

    const uint32_t* hp = (const uint32_t*)g_hp;
    const uint32_t* wp = (const uint32_t*)g_wp;
    #pragma unroll
    for (int i = 0; i < 16; i++) {                 // A: 128 rows x 32 uint32
        int lin = tid + i * 256;
        int row = lin >> 5, cp = lin & 31;
        int gm = m0 + row;
        uint32_t v = (gm < N) ? hp[gm * 32 + cp] : 0u;
        *(uint32_t*)((char*)sA + row * 144 + cp * 4) = v;
    }
    #pragma unroll
    for (int i = 0; i < 16; i++) {                 // B: 128 rows x 32 uint32
        int lin = tid + i * 256;
        int row = lin >> 5, cp = lin & 31;
        int gc = n0 + row;
        uint32_t v = (gc < NKV) ? wp[gc * 32 + cp] : 0u;
        *(uint32_t*)((char*)sB + row * 144 + cp * 4) = v;
    }
    __syncthreads();

    const int mband = (w & 3) * 32;
    const int nband = (w >> 2) * 64;
    const int quad  = lane >> 3;
    const int l7    = lane & 7;

    float acc[2][8][4];
    #pragma unroll
    for (int mt = 0; mt < 2; mt++)
        #pragma unroll
        for (int j = 0; j < 8; j++)
            #pragma unroll
            for (int q = 0; q < 4; q++) acc[mt][j][q] = 0.f;

    #pragma unroll
    for (int kk = 0; kk < 4; kk++) {
        uint32_t a[2][4];
        #pragma unroll
        for (int mt = 0; mt < 2; mt++) {
            int row  = mband + mt * 16 + (quad & 1) * 8 + l7;
            int boff = row * 144 + (kk * 16 + (quad >> 1) * 8) * 2;
            uint32_t addr = smem_u32((const char*)sA + boff);
            LDSM_X4(a[mt][0], a[mt][1], a[mt][2], a[mt][3], addr);
        }
        #pragma unroll
        for (int jp = 0; jp < 4; jp++) {
            int col  = nband + jp * 16 + (quad >> 1) * 8 + l7;
            int boff = col * 144 + (kk * 16 + (quad & 1) * 8) * 2;
            uint32_t bb[4];
            uint32_t addr = smem_u32((const char*)sB + boff);
            LDSM_X4(bb[0], bb[1], bb[2], bb[3], addr);
            #pragma unroll
            for (int t2 = 0; t2 < 2; t2++) {
                int j = jp * 2 + t2;
                #pragma unroll
                for (int mt = 0; mt < 2; mt++)
                    mma_f16(acc[mt][j], a[mt], &bb[t2 * 2]);
            }
        }
    }

    // Direct epilogue, fp16 half2 stores
    #pragma unroll
    for (int mt = 0; mt < 2; mt++) {
        #pragma unroll
        for (int half = 0; half < 2; half++) {
            int gm = m0 + mband + mt * 16 + half * 8 + tq;
            if (gm >= N) continue;
            __half* vrow = g_V + (size_t)gm * NKV;
            #pragma unroll
            for (int j = 0; j < 8; j++) {
                int gc = n0 + nband + j * 8 + 2 * tr;
                if (gc >= NKV) continue;
                __half2 v = __floats2half2_rn(acc[mt][j][half * 2 + 0],
                                              acc[mt][j][half * 2 + 1]);
                *(__half2*)(vrow + gc) = v;
            }
        }
    }
}

// ---------------------------------------------------------------------------
// Counting-sort scan + scatter.
__global__ void scanA_kernel() {
    __shared__ int buf[256];
    int b = blockIdx.x, t = threadIdx.x;
    int i = b * 256 + t;
    int v = (i < NBINS) ? g_cnt[i] : 0;
    buf[t] = v; __syncthreads();
    #pragma unroll
    for (int o = 1; o < 256; o <<= 1) {
        int u = (t >= o) ? buf[t - o] : 0;
        __syncthreads();
        buf[t] += u;
        __syncthreads();
    }
    if (i < NBINS) g_off[i] = buf[t] - v;
    if (t == 255) g_bsum[b] = buf[255];
}

__global__ void scanB_kernel() {
    __shared__ int buf[256];
    int t = threadIdx.x;
    int v = (t < SCAN_NB) ? g_bsum[t] : 0;
    buf[t] = v; __syncthreads();
    #pragma unroll
    for (int o = 1; o < 256; o <<= 1) {
        int u = (t >= o) ? buf[t - o] : 0;
        __syncthreads();
        buf[t] += u;
        __syncthreads();
    }
    if (t < SCAN_NB) g_boff[t] = buf[t] - v;
}

__global__ void scanC_kernel() {
    int i = blockIdx.x * blockDim.x + threadIdx.x;
    if (i < NBINS) g_off[i] += g_boff[i >> 8];
}

__global__ void scatter_kernel(int M) {
    int i = blockIdx.x * blockDim.x + threadIdx.x;
    if (i >= M) return;
    int pos = atomicAdd(&g_off[g_tgt[i]], 1);
    g_eord[pos] = i;
}

// ---------------------------------------------------------------------------
// Stage 2: warp per edge (sorted by tgt). fp16 V, uint2 (4-half) loads.
__global__ __launch_bounds__(256) void edge_msg_kernel(const float* __restrict__ ea, int M)
{
    int w    = blockIdx.x * 8 + (threadIdx.x >> 5);
    int lane = threadIdx.x & 31;
    if (w >= M) return;
    int m = g_eord[w];

    const int half = lane >> 4;        // 0: even d, 1: odd d
    const int q    = lane & 15;        // owns cols q*4 .. q*4+3

    float eav = ea[(size_t)m * 32 + lane];
    int t = g_tgt[m], s = g_src[m];
    const uint2* Vt = (const uint2*)(g_V + (size_t)t * NKV);   // uint2 = 4 halfs

    float4 acc = make_float4(0.f, 0.f, 0.f, 0.f);
    #pragma unroll
    for (int dd = 0; dd < 16; dd++) {
        int d = dd * 2 + half;
        uint2 u = Vt[d * 16 + q];
        float2 v01 = __half22float2(*(const __half2*)&u.x);
        float2 v23 = __half22float2(*(const __half2*)&u.y);
        float a = __shfl_sync(0xffffffffu, eav, d);
        acc.x += a * v01.x; acc.y += a * v01.y;
        acc.z += a * v23.x; acc.w += a * v23.y;
    }
    if (half == 0) {                   // bias row d=32, add once
        uint2 u = Vt[32 * 16 + q];
        float2 v01 = __half22float2(*(const __half2*)&u.x);
        float2 v23 = __half22float2(*(const __half2*)&u.y);
        acc.x += v01.x; acc.y += v01.y; acc.z += v23.x; acc.w += v23.y;
    }
    acc.x += __shfl_xor_sync(0xffffffffu, acc.x, 16);
    acc.y += __shfl_xor_sync(0xffffffffu, acc.y, 16);
    acc.z += __shfl_xor_sync(0xffffffffu, acc.z, 16);
    acc.w += __shfl_xor_sync(0xffffffffu, acc.w, 16);

    float* base = &g_aggr[(size_t)s * 64 + q * 4];
    if (half == 0) { atomicAdd(base + 0, acc.x); atomicAdd(base + 1, acc.y); }
    else           { atomicAdd(base + 2, acc.z); atomicAdd(base + 3, acc.w); }
}

// ---------------------------------------------------------------------------
__global__ void ln_kernel(const float* __restrict__ gamma,
                          const float* __restrict__ beta,
                          float* __restrict__ out, int N)
{
    int row  = blockIdx.x * 8 + (threadIdx.x >> 5);
    int lane = threadIdx.x & 31;
    if (row >= N) return;
    float x0 = g_aggr[row * 64 + lane];
    float x1 = g_aggr[row * 64 + 32 + lane];
    float s = x0 + x1;
    #pragma unroll
    for (int o = 16; o > 0; o >>= 1) s += __shfl_xor_sync(0xffffffffu, s, o);
    float mu = s * (1.f / 64.f);
    float d0 = x0 - mu, d1 = x1 - mu;
    float v = d0 * d0 + d1 * d1;
    #pragma unroll
    for (int o = 16; o > 0; o >>= 1) v += __shfl_xor_sync(0xffffffffu, v, o);
    float inv = rsqrtf(v * (1.f / 64.f) + 1e-5f);
    out[row * 64 + lane]      = d0 * inv * gamma[lane]      + beta[lane];
    out[row * 64 + 32 + lane] = d1 * inv * gamma[lane + 32] + beta[lane + 32];
}

// ---------------------------------------------------------------------------
extern "C" void kernel_launch(void* const* d_in, const int* in_sizes, int n_in,
                              void* d_out, int out_size) {
    const float* h     = (const float*)d_in[0];
    const float* ea    = (const float*)d_in[1];
    const float* W     = (const float*)d_in[2];
    const float* b     = (const float*)d_in[3];
    const float* gamma = (const float*)d_in[4];
    const float* beta  = (const float*)d_in[5];
    const void*  eidx  = d_in[6];

    int n64_seen = 0;
    for (int i = 0; i < n_in; i++) {
        switch (in_sizes[i]) {
            case 3200000: h    = (const float*)d_in[i]; break;
            case 4800000: ea   = (const float*)d_in[i]; break;
            case 131072:  W    = (const float*)d_in[i]; break;
            case 4096:    b    = (const float*)d_in[i]; break;
            case 300000:  eidx = d_in[i];               break;
            case 64:
                if (n64_seen++ == 0) gamma = (const float*)d_in[i];
                else                 beta  = (const float*)d_in[i];
                break;
            default: break;
        }
    }

    const int N = 50000;
    const int M = 150000;
    float* out = (float*)d_out;

    probe_idx_kernel<<<1, 1>>>((const int*)eidx, M);                     // 1
    pack_h_init_kernel<<<(N * EMB + 255) / 256, 256>>>(h, N * EMB);      // 2
    pack_w_zero_kernel<<<(NKV * EMB + 255) / 256, 256>>>(W, b);          // 3

    dim3 g1((N + 127) / 128, (NKV + 127) / 128);                         // 391 x 17
    node_v_mma_kernel<<<g1, 256>>>(N);                                   // 4 (profiled slot)

    convert_hist_kernel<<<(M + 255) / 256, 256>>>(eidx, M);              // 5
    scanA_kernel<<<SCAN_NB, 256>>>();
    scanB_kernel<<<1, 256>>>();
    scanC_kernel<<<(NBINS + 255) / 256, 256>>>();
    scatter_kernel<<<(M + 255) / 256, 256>>>(M);

    edge_msg_kernel<<<(M + 7) / 8, 256>>>(ea, M);
    ln_kernel<<<(N + 7) / 8, 256>>>(gamma, beta, out, N);
}

// round 15
// speedup vs baseline: 1.3307x; 1.3307x over previous
#include <cuda_runtime.h>
#include <cuda_fp16.h>
#include <cstdint>

#define EMB 64
#define IN_DIM 32
#define NKV 2112              // (IN_DIM+1)*EMB : V col c = d*64+e, d=32 -> bias
#define MAX_NODES 50000
#define MAX_EDGES 150000
#define NBINS MAX_NODES
#define SCAN_NB ((NBINS + 255) / 256)

// Scratch (__device__ globals; allocation-free rule)
__device__ __half g_hp[MAX_NODES * EMB];           // fp16 h
__device__ __half g_wp[NKV * EMB];                 // fp16 W3T, [c][f]
__device__ __half g_V[(size_t)MAX_NODES * NKV];    // fp16 V (~211 MB)
__device__ float g_aggr[MAX_NODES * EMB];
__device__ int   g_src[MAX_EDGES];
__device__ int   g_tgt[MAX_EDGES];
__device__ int   g_eord[MAX_EDGES];
__device__ int   g_cnt[NBINS];
__device__ int   g_off[NBINS];
__device__ int   g_bsum[SCAN_NB];
__device__ int   g_boff[SCAN_NB];
__device__ int   g_idx_is64;

__device__ __forceinline__ uint32_t smem_u32(const void* p) {
    uint32_t a;
    asm("{ .reg .u64 t; cvta.to.shared.u64 t, %1; cvt.u32.u64 %0, t; }" : "=r"(a) : "l"(p));
    return a;
}

// ---------------------------------------------------------------------------
__global__ void probe_idx_kernel(const int* __restrict__ ei32, int M) {
    int n = 2 * M;
    int is64 = 1;
    for (int i = 1; i < 256 && i < n; i += 2)
        if (ei32[i] != 0) { is64 = 0; break; }
    g_idx_is64 = is64;
}

// Convert indices AND build the tgt histogram in the same pass.
__global__ void convert_hist_kernel(const void* __restrict__ eidx, int M) {
    int i = blockIdx.x * blockDim.x + threadIdx.x;
    if (i >= M) return;
    int s, t;
    if (g_idx_is64) {
        const long long* p = (const long long*)eidx;
        s = (int)p[i];
        t = (int)p[M + i];
    } else {
        const int* p = (const int*)eidx;
        s = p[i];
        t = p[M + i];
    }
    g_src[i] = s;
    g_tgt[i] = t;
    atomicAdd(&g_cnt[t], 1);
}

// Fused: fp16 h AND residual init of aggr (h read once).
__global__ void pack_h_init_kernel(const float* __restrict__ h, int n) {
    int i = blockIdx.x * blockDim.x + threadIdx.x;
    if (i >= n) return;
    float v = h[i];
    g_hp[i] = __float2half(v);
    g_aggr[i] = v;
}

// col c=(d,e): d<32 -> W[(e*64+f)*32+d] ; d==32 -> b[e*64+f]
// Also zeroes the sort histograms (saves a launch).
__global__ void pack_w_zero_kernel(const float* __restrict__ W, const float* __restrict__ b) {
    int idx = blockIdx.x * blockDim.x + threadIdx.x;
    if (idx < NBINS) g_cnt[idx] = 0;
    if (idx < SCAN_NB) g_bsum[idx] = 0;
    if (idx >= NKV * EMB) return;
    int c = idx >> 6, f = idx & 63;
    int d = c >> 6, e = c & 63;
    float w = (d < 32) ? W[(e * 64 + f) * 32 + d] : b[e * 64 + f];
    g_wp[idx] = __float2half(w);
}

// ---------------------------------------------------------------------------
// Stage 1: V = h @ W3T via single-pass mma.sync m16n8k16 fp16 (fp32 accum).
// Block tile 128m x 64n, 256 threads, 8 warps each 16m x 64n (32 acc regs).
// Target 4 CTAs/SM for latency hiding.
__device__ __forceinline__ void mma_f16(float* d, const uint32_t* a, const uint32_t* b) {
    asm volatile(
        "mma.sync.aligned.m16n8k16.row.col.f32.f16.f16.f32 "
        "{%0,%1,%2,%3}, {%4,%5,%6,%7}, {%8,%9}, {%0,%1,%2,%3};"
        : "+f"(d[0]), "+f"(d[1]), "+f"(d[2]), "+f"(d[3])
        : "r"(a[0]), "r"(a[1]), "r"(a[2]), "r"(a[3]), "r"(b[0]), "r"(b[1]));
}
#define LDSM_X4(r0,r1,r2,r3,addr) \
    asm volatile("ldmatrix.sync.aligned.m8n8.x4.shared.b16 {%0,%1,%2,%3}, [%4];" \
        : "=r"(r0), "=r"(r1), "=r"(r2), "=r"(r3) : "r"(addr))

__global__ __launch_bounds__(256, 4) void node_v_mma_kernel(int N)
{
    __shared__ __align__(16) __half sA[128 * 72];   // 128 rows x 144B
    __shared__ __align__(16) __half sB[64 * 72];    // 64 rows x 144B

    const int tid  = threadIdx.x;
    const int w    = tid >> 5;
    const int lane = tid & 31;
    const int tq   = lane >> 2;
    const int tr   = lane & 3;
    const int quad = lane >> 3;
    const int l7   = lane & 7;
    const int m0   = blockIdx.x * 128;
    const int n0   = blockIdx.y * 64;

    const uint32_t* hp = (const uint32_t*)g_hp;
    const uint32_t* wp = (const uint32_t*)g_wp;
    #pragma unroll
    for (int i = 0; i < 16; i++) {                 // A: 128 rows x 32 uint32
        int lin = tid + i * 256;
        int row = lin >> 5, cp = lin & 31;
        int gm = m0 + row;
        uint32_t v = (gm < N) ? hp[gm * 32 + cp] : 0u;
        *(uint32_t*)((char*)sA + row * 144 + cp * 4) = v;
    }
    #pragma unroll
    for (int i = 0; i < 8; i++) {                  // B: 64 rows x 32 uint32
        int lin = tid + i * 256;
        int row = lin >> 5, cp = lin & 31;
        int gc = n0 + row;
        uint32_t v = (gc < NKV) ? wp[gc * 32 + cp] : 0u;
        *(uint32_t*)((char*)sB + row * 144 + cp * 4) = v;
    }
    __syncthreads();

    const int mband = w * 16;                      // warp's 16-node band

    float acc[8][4];
    #pragma unroll
    for (int j = 0; j < 8; j++)
        #pragma unroll
        for (int q = 0; q < 4; q++) acc[j][q] = 0.f;

    #pragma unroll
    for (int kk = 0; kk < 4; kk++) {
        uint32_t a[4];
        {
            int row  = mband + (quad & 1) * 8 + l7;
            int boff = row * 144 + (kk * 16 + (quad >> 1) * 8) * 2;
            uint32_t addr = smem_u32((const char*)sA + boff);
            LDSM_X4(a[0], a[1], a[2], a[3], addr);
        }
        #pragma unroll
        for (int jp = 0; jp < 4; jp++) {
            int col  = jp * 16 + (quad >> 1) * 8 + l7;
            int boff = col * 144 + (kk * 16 + (quad & 1) * 8) * 2;
            uint32_t bb[4];
            uint32_t addr = smem_u32((const char*)sB + boff);
            LDSM_X4(bb[0], bb[1], bb[2], bb[3], addr);
            mma_f16(acc[jp * 2 + 0], a, &bb[0]);
            mma_f16(acc[jp * 2 + 1], a, &bb[2]);
        }
    }

    // Direct epilogue, fp16 half2 stores
    #pragma unroll
    for (int half = 0; half < 2; half++) {
        int gm = m0 + mband + half * 8 + tq;
        if (gm >= N) continue;
        __half* vrow = g_V + (size_t)gm * NKV;
        #pragma unroll
        for (int j = 0; j < 8; j++) {
            int gc = n0 + j * 8 + 2 * tr;
            if (gc >= NKV) continue;
            __half2 v = __floats2half2_rn(acc[j][half * 2 + 0],
                                          acc[j][half * 2 + 1]);
            *(__half2*)(vrow + gc) = v;
        }
    }
}

// ---------------------------------------------------------------------------
// Counting-sort scan + scatter.
__global__ void scanA_kernel() {
    __shared__ int buf[256];
    int b = blockIdx.x, t = threadIdx.x;
    int i = b * 256 + t;
    int v = (i < NBINS) ? g_cnt[i] : 0;
    buf[t] = v; __syncthreads();
    #pragma unroll
    for (int o = 1; o < 256; o <<= 1) {
        int u = (t >= o) ? buf[t - o] : 0;
        __syncthreads();
        buf[t] += u;
        __syncthreads();
    }
    if (i < NBINS) g_off[i] = buf[t] - v;
    if (t == 255) g_bsum[b] = buf[255];
}

__global__ void scanB_kernel() {
    __shared__ int buf[256];
    int t = threadIdx.x;
    int v = (t < SCAN_NB) ? g_bsum[t] : 0;
    buf[t] = v; __syncthreads();
    #pragma unroll
    for (int o = 1; o < 256; o <<= 1) {
        int u = (t >= o) ? buf[t - o] : 0;
        __syncthreads();
        buf[t] += u;
        __syncthreads();
    }
    if (t < SCAN_NB) g_boff[t] = buf[t] - v;
}

__global__ void scanC_kernel() {
    int i = blockIdx.x * blockDim.x + threadIdx.x;
    if (i < NBINS) g_off[i] += g_boff[i >> 8];
}

__global__ void scatter_kernel(int M) {
    int i = blockIdx.x * blockDim.x + threadIdx.x;
    if (i >= M) return;
    int pos = atomicAdd(&g_off[g_tgt[i]], 1);
    g_eord[pos] = i;
}

// ---------------------------------------------------------------------------
// Stage 2: warp per edge (sorted by tgt). fp16 V, uint2 (4-half) loads.
__global__ __launch_bounds__(256) void edge_msg_kernel(const float* __restrict__ ea, int M)
{
    int w    = blockIdx.x * 8 + (threadIdx.x >> 5);
    int lane = threadIdx.x & 31;
    if (w >= M) return;
    int m = g_eord[w];

    const int half = lane >> 4;        // 0: even d, 1: odd d
    const int q    = lane & 15;        // owns cols q*4 .. q*4+3

    float eav = ea[(size_t)m * 32 + lane];
    int t = g_tgt[m], s = g_src[m];
    const uint2* Vt = (const uint2*)(g_V + (size_t)t * NKV);   // uint2 = 4 halfs

    float4 acc = make_float4(0.f, 0.f, 0.f, 0.f);
    #pragma unroll
    for (int dd = 0; dd < 16; dd++) {
        int d = dd * 2 + half;
        uint2 u = Vt[d * 16 + q];
        float2 v01 = __half22float2(*(const __half2*)&u.x);
        float2 v23 = __half22float2(*(const __half2*)&u.y);
        float a = __shfl_sync(0xffffffffu, eav, d);
        acc.x += a * v01.x; acc.y += a * v01.y;
        acc.z += a * v23.x; acc.w += a * v23.y;
    }
    if (half == 0) {                   // bias row d=32, add once
        uint2 u = Vt[32 * 16 + q];
        float2 v01 = __half22float2(*(const __half2*)&u.x);
        float2 v23 = __half22float2(*(const __half2*)&u.y);
        acc.x += v01.x; acc.y += v01.y; acc.z += v23.x; acc.w += v23.y;
    }
    acc.x += __shfl_xor_sync(0xffffffffu, acc.x, 16);
    acc.y += __shfl_xor_sync(0xffffffffu, acc.y, 16);
    acc.z += __shfl_xor_sync(0xffffffffu, acc.z, 16);
    acc.w += __shfl_xor_sync(0xffffffffu, acc.w, 16);

    float* base = &g_aggr[(size_t)s * 64 + q * 4];
    if (half == 0) { atomicAdd(base + 0, acc.x); atomicAdd(base + 1, acc.y); }
    else           { atomicAdd(base + 2, acc.z); atomicAdd(base + 3, acc.w); }
}

// ---------------------------------------------------------------------------
__global__ void ln_kernel(const float* __restrict__ gamma,
                          const float* __restrict__ beta,
                          float* __restrict__ out, int N)
{
    int row  = blockIdx.x * 8 + (threadIdx.x >> 5);
    int lane = threadIdx.x & 31;
    if (row >= N) return;
    float x0 = g_aggr[row * 64 + lane];
    float x1 = g_aggr[row * 64 + 32 + lane];
    float s = x0 + x1;
    #pragma unroll
    for (int o = 16; o > 0; o >>= 1) s += __shfl_xor_sync(0xffffffffu, s, o);
    float mu = s * (1.f / 64.f);
    float d0 = x0 - mu, d1 = x1 - mu;
    float v = d0 * d0 + d1 * d1;
    #pragma unroll
    for (int o = 16; o > 0; o >>= 1) v += __shfl_xor_sync(0xffffffffu, v, o);
    float inv = rsqrtf(v * (1.f / 64.f) + 1e-5f);
    out[row * 64 + lane]      = d0 * inv * gamma[lane]      + beta[lane];
    out[row * 64 + 32 + lane] = d1 * inv * gamma[lane + 32] + beta[lane + 32];
}

// ---------------------------------------------------------------------------
extern "C" void kernel_launch(void* const* d_in, const int* in_sizes, int n_in,
                              void* d_out, int out_size) {
    const float* h     = (const float*)d_in[0];
    const float* ea    = (const float*)d_in[1];
    const float* W     = (const float*)d_in[2];
    const float* b     = (const float*)d_in[3];
    const float* gamma = (const float*)d_in[4];
    const float* beta  = (const float*)d_in[5];
    const void*  eidx  = d_in[6];

    int n64_seen = 0;
    for (int i = 0; i < n_in; i++) {
        switch (in_sizes[i]) {
            case 3200000: h    = (const float*)d_in[i]; break;
            case 4800000: ea   = (const float*)d_in[i]; break;
            case 131072:  W    = (const float*)d_in[i]; break;
            case 4096:    b    = (const float*)d_in[i]; break;
            case 300000:  eidx = d_in[i];               break;
            case 64:
                if (n64_seen++ == 0) gamma = (const float*)d_in[i];
                else                 beta  = (const float*)d_in[i];
                break;
            default: break;
        }
    }

    const int N = 50000;
    const int M = 150000;
    float* out = (float*)d_out;

    probe_idx_kernel<<<1, 1>>>((const int*)eidx, M);                     // 1
    pack_h_init_kernel<<<(N * EMB + 255) / 256, 256>>>(h, N * EMB);      // 2
    pack_w_zero_kernel<<<(NKV * EMB + 255) / 256, 256>>>(W, b);          // 3

    dim3 g1((N + 127) / 128, (NKV + 63) / 64);                           // 391 x 33
    node_v_mma_kernel<<<g1, 256>>>(N);                                   // 4 (profiled slot)

    convert_hist_kernel<<<(M + 255) / 256, 256>>>(eidx, M);              // 5
    scanA_kernel<<<SCAN_NB, 256>>>();
    scanB_kernel<<<1, 256>>>();
    scanC_kernel<<<(NBINS + 255) / 256, 256>>>();
    scatter_kernel<<<(M + 255) / 256, 256>>>(M);

    edge_msg_kernel<<<(M + 7) / 8, 256>>>(ea, M);
    ln_kernel<<<(N + 7) / 8, 256>>>(gamma, beta, out, N);
}